// round 2
// baseline (speedup 1.0000x reference)
#include <cuda_runtime.h>
#include <math.h>

#define B_  4
#define C_  128
#define N_  4096      // 64*64 spatial
#define NG  8         // partial-sum groups for the mean

// ---------------- scratch (device globals: sanctioned, no allocs) ----------
__device__ float    g_part[B_ * NG * C_];
__device__ float    g_mean[B_ * C_];
__device__ float    g_X[(size_t)B_ * N_ * C_];     // normalized fx, [b][n][c]
__device__ float    g_Y[(size_t)B_ * N_ * C_];     // normalized fy, [b][n][c]
__device__ float    g_S[(size_t)B_ * N_ * N_];     // similarity s[b][n][m] (256 MB)
__device__ unsigned g_rowmax[B_ * N_];             // bit-encoded fp32 row max
__device__ float    g_A[B_ * N_];                  // per-row max(A) values

// monotone fp32 <-> uint encoding (exact, order-independent max)
__device__ __forceinline__ unsigned encf(float f) {
    unsigned u = __float_as_uint(f);
    return (u & 0x80000000u) ? ~u : (u | 0x80000000u);
}
__device__ __forceinline__ float decf(unsigned v) {
    return (v & 0x80000000u) ? __uint_as_float(v ^ 0x80000000u)
                             : __uint_as_float(~v);
}

// ---------------- kernel 1a: partial spatial sums of feature_y -------------
__global__ void k_mean_part(const float* __restrict__ fy) {
    int b = blockIdx.y, g = blockIdx.x, c = threadIdx.x;   // 128 threads
    const float* p = fy + ((size_t)b * N_ + (size_t)g * (N_ / NG)) * C_ + c;
    float s = 0.f;
    for (int n = 0; n < N_ / NG; ++n) s += p[(size_t)n * C_];
    g_part[(b * NG + g) * C_ + c] = s;
}

// ---------------- kernel 1b: finalize mean ---------------------------------
__global__ void k_mean_final() {
    int b = blockIdx.x, c = threadIdx.x;
    float s = 0.f;
    #pragma unroll
    for (int g = 0; g < NG; ++g) s += g_part[(b * NG + g) * C_ + c];
    g_mean[b * C_ + c] = s * (1.0f / N_);
}

// ---------------- kernel 2: center + L2-normalize per pixel ----------------
// one warp per (b,n); each lane owns 4 contiguous channels (float4)
__global__ __launch_bounds__(256) void k_normalize(const float* __restrict__ fx,
                                                   const float* __restrict__ fy) {
    int w    = blockIdx.x * 8 + (threadIdx.x >> 5);
    int lane = threadIdx.x & 31;
    int b = w / N_, n = w % N_;
    size_t base = ((size_t)b * N_ + n) * C_ + lane * 4;
    float4 xv = *(const float4*)(fx + base);
    float4 yv = *(const float4*)(fy + base);
    float4 mv = *(const float4*)(g_mean + b * C_ + lane * 4);
    float4 cx = make_float4(xv.x - mv.x, xv.y - mv.y, xv.z - mv.z, xv.w - mv.w);
    float4 cy = make_float4(yv.x - mv.x, yv.y - mv.y, yv.z - mv.z, yv.w - mv.w);
    float ssx = cx.x*cx.x + cx.y*cx.y + cx.z*cx.z + cx.w*cx.w;
    float ssy = cy.x*cy.x + cy.y*cy.y + cy.z*cy.z + cy.w*cy.w;
    #pragma unroll
    for (int o = 16; o; o >>= 1) {
        ssx += __shfl_xor_sync(0xffffffffu, ssx, o);
        ssy += __shfl_xor_sync(0xffffffffu, ssy, o);
    }
    float sx = 1.0f / (sqrtf(ssx) + 1e-10f);
    float sy = 1.0f / (sqrtf(ssy) + 1e-10f);
    *(float4*)(g_X + base) = make_float4(cx.x*sx, cx.y*sx, cx.z*sx, cx.w*sx);
    *(float4*)(g_Y + base) = make_float4(cy.x*sy, cy.y*sy, cy.z*sy, cy.w*sy);
}

// ---------------- kernel 3a: reset row-max ---------------------------------
__global__ void k_initmax() {
    int i = blockIdx.x * blockDim.x + threadIdx.x;
    if (i < B_ * N_) g_rowmax[i] = 0u;   // encodes below any real float
}

// ---------------- kernel 3b: SGEMM S = X * Y^T + rowwise max ---------------
// 128x128 block tile, BK=8, 256 threads, 8x8 per thread
__global__ __launch_bounds__(256) void k_gemm() {
    const int b  = blockIdx.z;
    const int n0 = blockIdx.y * 128;
    const int m0 = blockIdx.x * 128;
    const float* Xb = g_X + (size_t)b * N_ * C_;
    const float* Yb = g_Y + (size_t)b * N_ * C_;
    __shared__ float As[8][128];
    __shared__ float Bs[8][128];
    const int tid  = threadIdx.x;
    const int trow = tid >> 4;         // 0..15  (n blocks of 8)
    const int tcol = tid & 15;         // 0..15  (m blocks of 8)
    const int lrow = tid >> 1;         // 0..127 load row
    const int lk4  = (tid & 1) * 4;    // 0 or 4

    float acc[8][8];
    #pragma unroll
    for (int i = 0; i < 8; ++i)
        #pragma unroll
        for (int j = 0; j < 8; ++j) acc[i][j] = 0.f;

    for (int kt = 0; kt < C_; kt += 8) {
        float4 av = *(const float4*)(Xb + (size_t)(n0 + lrow) * C_ + kt + lk4);
        float4 bv = *(const float4*)(Yb + (size_t)(m0 + lrow) * C_ + kt + lk4);
        __syncthreads();
        As[lk4+0][lrow] = av.x; As[lk4+1][lrow] = av.y;
        As[lk4+2][lrow] = av.z; As[lk4+3][lrow] = av.w;
        Bs[lk4+0][lrow] = bv.x; Bs[lk4+1][lrow] = bv.y;
        Bs[lk4+2][lrow] = bv.z; Bs[lk4+3][lrow] = bv.w;
        __syncthreads();
        #pragma unroll
        for (int k = 0; k < 8; ++k) {
            float ra[8], rb[8];
            *(float4*)(ra)     = *(const float4*)&As[k][trow * 8];
            *(float4*)(ra + 4) = *(const float4*)&As[k][trow * 8 + 4];
            *(float4*)(rb)     = *(const float4*)&Bs[k][tcol * 8];
            *(float4*)(rb + 4) = *(const float4*)&Bs[k][tcol * 8 + 4];
            #pragma unroll
            for (int i = 0; i < 8; ++i)
                #pragma unroll
                for (int j = 0; j < 8; ++j)
                    acc[i][j] = fmaf(ra[i], rb[j], acc[i][j]);
        }
    }

    float* Sb = g_S + ((size_t)b * N_ + n0) * N_ + m0;
    #pragma unroll
    for (int i = 0; i < 8; ++i) {
        int n = trow * 8 + i;
        *(float4*)(Sb + (size_t)n * N_ + tcol * 8)     =
            make_float4(acc[i][0], acc[i][1], acc[i][2], acc[i][3]);
        *(float4*)(Sb + (size_t)n * N_ + tcol * 8 + 4) =
            make_float4(acc[i][4], acc[i][5], acc[i][6], acc[i][7]);
        float mx = acc[i][0];
        #pragma unroll
        for (int j = 1; j < 8; ++j) mx = fmaxf(mx, acc[i][j]);
        // reduce over the 16 lanes owning this row (same half-warp)
        #pragma unroll
        for (int o = 8; o; o >>= 1)
            mx = fmaxf(mx, __shfl_xor_sync(0xffffffffu, mx, o));
        if (tcol == 0) atomicMax(&g_rowmax[b * N_ + n0 + n], encf(mx));
    }
}

// ---------------- kernel 4: per-row softmax epilogue -----------------------
// one 128-thread block per row; w = exp((1 - (1-s)/(dmin+eps))/h)
__global__ __launch_bounds__(128) void k_rowpost() {
    const int row = blockIdx.x;                // 0 .. B_*N_-1
    const float* Sr = g_S + (size_t)row * N_;
    const float smax = decf(g_rowmax[row]);
    const float dmin = 1.0f - smax;
    const float inv  = 1.0f / (dmin + 0.001f);
    const int tid = threadIdx.x;

    float sum = 0.f, wmx = 0.f;
    #pragma unroll
    for (int it = 0; it < N_ / (128 * 4); ++it) {
        float4 sv = *(const float4*)(Sr + (size_t)(it * 128 + tid) * 4);
        float w0 = __expf((1.0f - (1.0f - sv.x) * inv) * 10.0f);
        float w1 = __expf((1.0f - (1.0f - sv.y) * inv) * 10.0f);
        float w2 = __expf((1.0f - (1.0f - sv.z) * inv) * 10.0f);
        float w3 = __expf((1.0f - (1.0f - sv.w) * inv) * 10.0f);
        sum += (w0 + w1) + (w2 + w3);
        wmx = fmaxf(wmx, fmaxf(fmaxf(w0, w1), fmaxf(w2, w3)));
    }
    __shared__ float ssum[128], smx[128];
    ssum[tid] = sum; smx[tid] = wmx;
    __syncthreads();
    #pragma unroll
    for (int s = 64; s; s >>= 1) {
        if (tid < s) {
            ssum[tid] += ssum[tid + s];
            smx[tid]   = fmaxf(smx[tid], smx[tid + s]);
        }
        __syncthreads();
    }
    if (tid == 0) g_A[row] = smx[0] / ssum[0];
}

// ---------------- kernel 5: final CX mean + -log ---------------------------
__global__ void k_final(float* __restrict__ out) {
    int b = blockIdx.x, tid = threadIdx.x;     // 128 threads
    float s = 0.f;
    #pragma unroll
    for (int k = 0; k < N_ / 128; ++k) s += g_A[b * N_ + k * 128 + tid];
    __shared__ float sh[128];
    sh[tid] = s; __syncthreads();
    #pragma unroll
    for (int r = 64; r; r >>= 1) {
        if (tid < r) sh[tid] += sh[tid + r];
        __syncthreads();
    }
    if (tid == 0) out[b] = -logf(sh[0] * (1.0f / N_));
}

// ---------------- launcher -------------------------------------------------
extern "C" void kernel_launch(void* const* d_in, const int* in_sizes, int n_in,
                              void* d_out, int out_size) {
    const float* fx = (const float*)d_in[0];
    const float* fy = (const float*)d_in[1];
    float* out = (float*)d_out;

    k_mean_part<<<dim3(NG, B_), 128>>>(fy);
    k_mean_final<<<B_, 128>>>();
    k_normalize<<<(B_ * N_) / 8, 256>>>(fx, fy);
    k_initmax<<<(B_ * N_ + 255) / 256, 256>>>();
    k_gemm<<<dim3(N_ / 128, N_ / 128, B_), 256>>>();
    k_rowpost<<<B_ * N_, 128>>>();
    k_final<<<B_, 128>>>(out);
}

// round 6
// speedup vs baseline: 2.5611x; 2.5611x over previous
#include <cuda_runtime.h>
#include <cuda_fp16.h>
#include <math.h>
#include <stdint.h>

#define B_  4
#define C_  128
#define N_  4096
#define NG  8

// ---------------- scratch (device globals; no allocs) ----------------------
__device__ float   g_part[B_ * NG * C_];
__device__ float   g_mean[B_ * C_];
__device__ __half  g_X[(size_t)B_ * N_ * C_];     // normalized fx, fp16 [b][n][c]
__device__ __half  g_Y[(size_t)B_ * N_ * C_];     // normalized fy, fp16 [b][n][c]
__device__ __half  g_S[(size_t)B_ * N_ * N_];     // similarity, fp16 (128 MB)
__device__ float   g_A[B_ * N_];                  // per-row max(A)

// ---------------- warp MMA helpers (sm_80 PTX: works on compute_103) -------
__device__ __forceinline__ uint32_t smem_to_u32(const void* p) {
    uint32_t a;
    asm("{ .reg .u64 t; cvta.to.shared.u64 t, %1; cvt.u32.u64 %0, t; }"
        : "=r"(a) : "l"(p));
    return a;
}
__device__ __forceinline__ void ldsm4(uint32_t r[4], uint32_t addr) {
    asm volatile("ldmatrix.sync.aligned.m8n8.x4.shared.b16 {%0,%1,%2,%3}, [%4];"
                 : "=r"(r[0]), "=r"(r[1]), "=r"(r[2]), "=r"(r[3]) : "r"(addr));
}
__device__ __forceinline__ void mma16816(float c[4], const uint32_t a[4],
                                         const uint32_t b[2]) {
    asm volatile("mma.sync.aligned.m16n8k16.row.col.f32.f16.f16.f32 "
                 "{%0,%1,%2,%3}, {%4,%5,%6,%7}, {%8,%9}, {%0,%1,%2,%3};"
                 : "+f"(c[0]), "+f"(c[1]), "+f"(c[2]), "+f"(c[3])
                 : "r"(a[0]), "r"(a[1]), "r"(a[2]), "r"(a[3]),
                   "r"(b[0]), "r"(b[1]));
}

// ---------------- kernel 1a/1b: spatial mean of feature_y ------------------
__global__ void k_mean_part(const float* __restrict__ fy) {
    int b = blockIdx.y, g = blockIdx.x, c = threadIdx.x;
    const float* p = fy + ((size_t)b * N_ + (size_t)g * (N_ / NG)) * C_ + c;
    float s = 0.f;
    for (int n = 0; n < N_ / NG; ++n) s += p[(size_t)n * C_];
    g_part[(b * NG + g) * C_ + c] = s;
}
__global__ void k_mean_final() {
    int b = blockIdx.x, c = threadIdx.x;
    float s = 0.f;
    #pragma unroll
    for (int g = 0; g < NG; ++g) s += g_part[(b * NG + g) * C_ + c];
    g_mean[b * C_ + c] = s * (1.0f / N_);
}

// ---------------- kernel 2: center + L2-normalize -> fp16 ------------------
__global__ __launch_bounds__(256) void k_normalize(const float* __restrict__ fx,
                                                   const float* __restrict__ fy) {
    int w    = blockIdx.x * 8 + (threadIdx.x >> 5);
    int lane = threadIdx.x & 31;
    int b = w / N_, n = w % N_;
    size_t base = ((size_t)b * N_ + n) * C_ + lane * 4;
    float4 xv = *(const float4*)(fx + base);
    float4 yv = *(const float4*)(fy + base);
    float4 mv = *(const float4*)(g_mean + b * C_ + lane * 4);
    float cx[4] = {xv.x - mv.x, xv.y - mv.y, xv.z - mv.z, xv.w - mv.w};
    float cy[4] = {yv.x - mv.x, yv.y - mv.y, yv.z - mv.z, yv.w - mv.w};
    float ssx = cx[0]*cx[0] + cx[1]*cx[1] + cx[2]*cx[2] + cx[3]*cx[3];
    float ssy = cy[0]*cy[0] + cy[1]*cy[1] + cy[2]*cy[2] + cy[3]*cy[3];
    #pragma unroll
    for (int o = 16; o; o >>= 1) {
        ssx += __shfl_xor_sync(0xffffffffu, ssx, o);
        ssy += __shfl_xor_sync(0xffffffffu, ssy, o);
    }
    float sx = 1.0f / (sqrtf(ssx) + 1e-10f);
    float sy = 1.0f / (sqrtf(ssy) + 1e-10f);
    __half2 hx0 = __floats2half2_rn(cx[0]*sx, cx[1]*sx);
    __half2 hx1 = __floats2half2_rn(cx[2]*sx, cx[3]*sx);
    __half2 hy0 = __floats2half2_rn(cy[0]*sy, cy[1]*sy);
    __half2 hy1 = __floats2half2_rn(cy[2]*sy, cy[3]*sy);
    *(uint2*)(g_X + base) = make_uint2(*(uint32_t*)&hx0, *(uint32_t*)&hx1);
    *(uint2*)(g_Y + base) = make_uint2(*(uint32_t*)&hy0, *(uint32_t*)&hy1);
}

// ---------------- kernel 3: HMMA GEMM  S = X * Y^T  (fp16 out) -------------
// CTA: 128(n) x 128(m), full K=128 in SMEM. 8 warps = 4(n) x 2(m),
// warp tile 32(n) x 64(m) = 2 x 8 m16n8k16 tiles, 8 k-chunks.
#define SP     272u                 // padded smem row stride in bytes (136 halves)
#define TILE_B (128u * SP)          // 34816 bytes per tile
#define SM_GEMM (2u * TILE_B)       // 69632 bytes

__global__ __launch_bounds__(256, 2) void k_gemm_mma() {
    extern __shared__ char smem[];
    const int tid  = threadIdx.x;
    const int lane = tid & 31, wid = tid >> 5;
    const int b  = blockIdx.z;
    const int n0 = blockIdx.y * 128;
    const int m0 = blockIdx.x * 128;

    // ---- load X/Y tiles (row-major fp16, padded rows) ----
    {
        int row  = tid >> 1;            // 0..127
        int half = (tid & 1) * 128;     // byte offset within 256B row
        const char* gx = (const char*)(g_X + ((size_t)b * N_ + n0 + row) * C_) + half;
        const char* gy = (const char*)(g_Y + ((size_t)b * N_ + m0 + row) * C_) + half;
        char* sx = smem + row * SP + half;
        char* sy = smem + TILE_B + row * SP + half;
        #pragma unroll
        for (int i = 0; i < 8; ++i) {
            *(uint4*)(sx + i * 16) = *(const uint4*)(gx + i * 16);
            *(uint4*)(sy + i * 16) = *(const uint4*)(gy + i * 16);
        }
    }
    __syncthreads();

    const int wn0 = (wid & 3) * 32;     // warp n offset
    const int wm0 = (wid >> 2) * 64;    // warp m offset
    uint32_t as_u = smem_to_u32(smem);
    uint32_t bs_u = as_u + TILE_B;

    // ldmatrix source addresses (see fragment-mapping derivation)
    uint32_t aaddr = as_u + (uint32_t)(wn0 + (lane & 15)) * SP + (uint32_t)(lane >> 4) * 16u;
    uint32_t baddr = bs_u + (uint32_t)(wm0 + ((lane >> 4) & 1) * 8 + (lane & 7)) * SP
                          + (uint32_t)((lane >> 3) & 1) * 16u;

    float acc[2][8][4];
    #pragma unroll
    for (int i = 0; i < 2; ++i)
        #pragma unroll
        for (int j = 0; j < 8; ++j)
            #pragma unroll
            for (int k = 0; k < 4; ++k) acc[i][j][k] = 0.f;

    #pragma unroll
    for (int kc = 0; kc < 8; ++kc) {
        uint32_t koff = (uint32_t)kc * 32u;     // 16 halves per k-chunk
        uint32_t afr[2][4];
        ldsm4(afr[0], aaddr + koff);
        ldsm4(afr[1], aaddr + 16u * SP + koff);
        uint32_t bfr[8][2];
        #pragma unroll
        for (int p = 0; p < 4; ++p) {
            uint32_t r[4];
            ldsm4(r, baddr + (uint32_t)p * (16u * SP) + koff);
            bfr[2*p][0]   = r[0]; bfr[2*p][1]   = r[1];
            bfr[2*p+1][0] = r[2]; bfr[2*p+1][1] = r[3];
        }
        #pragma unroll
        for (int i = 0; i < 2; ++i)
            #pragma unroll
            for (int j = 0; j < 8; ++j)
                mma16816(acc[i][j], afr[i], bfr[j]);
    }

    // ---- epilogue: fp32 acc -> fp16 S ----
    __half* Sp = g_S + ((size_t)b * N_ + n0 + wn0) * N_ + m0 + wm0;
    #pragma unroll
    for (int i = 0; i < 2; ++i) {
        int r0 = i * 16 + (lane >> 2);
        #pragma unroll
        for (int j = 0; j < 8; ++j) {
            int c = j * 8 + (lane & 3) * 2;
            __half2 lo = __floats2half2_rn(acc[i][j][0], acc[i][j][1]);
            __half2 hi = __floats2half2_rn(acc[i][j][2], acc[i][j][3]);
            *(__half2*)(Sp + (size_t)r0 * N_ + c)       = lo;
            *(__half2*)(Sp + (size_t)(r0 + 8) * N_ + c) = hi;
        }
    }
}

// ---------------- kernel 4: per-row epilogue (fp16 S) ----------------------
// A_max = 1 / sum_m exp((s_m - smax) * t),  t = 10/(1.001 - smax)
__global__ __launch_bounds__(128) void k_rowpost() {
    const int row = blockIdx.x;
    const int tid = threadIdx.x;
    const uint4* Sr = (const uint4*)(g_S + (size_t)row * N_);

    float f[32];
    float mx = -1e30f;
    #pragma unroll
    for (int k = 0; k < 4; ++k) {
        uint4 v = Sr[tid + k * 128];
        uint32_t u[4] = {v.x, v.y, v.z, v.w};
        #pragma unroll
        for (int j = 0; j < 4; ++j) {
            float2 fv = __half22float2(*(__half2*)&u[j]);
            f[k * 8 + j * 2]     = fv.x;
            f[k * 8 + j * 2 + 1] = fv.y;
            mx = fmaxf(mx, fmaxf(fv.x, fv.y));
        }
    }
    __shared__ float red[128];
    red[tid] = mx; __syncthreads();
    #pragma unroll
    for (int s = 64; s; s >>= 1) {
        if (tid < s) red[tid] = fmaxf(red[tid], red[tid + s]);
        __syncthreads();
    }
    float smax = red[0];
    __syncthreads();
    float t = 10.0f / (1.001f - smax);
    float sum = 0.f;
    #pragma unroll
    for (int i = 0; i < 32; ++i) sum += __expf((f[i] - smax) * t);
    red[tid] = sum; __syncthreads();
    #pragma unroll
    for (int s = 64; s; s >>= 1) {
        if (tid < s) red[tid] += red[tid + s];
        __syncthreads();
    }
    if (tid == 0) g_A[row] = 1.0f / red[0];
}

// ---------------- kernel 5: final CX mean + -log ---------------------------
__global__ void k_final(float* __restrict__ out) {
    int b = blockIdx.x, tid = threadIdx.x;
    float s = 0.f;
    #pragma unroll
    for (int k = 0; k < N_ / 128; ++k) s += g_A[b * N_ + k * 128 + tid];
    __shared__ float sh[128];
    sh[tid] = s; __syncthreads();
    #pragma unroll
    for (int r = 64; r; r >>= 1) {
        if (tid < r) sh[tid] += sh[tid + r];
        __syncthreads();
    }
    if (tid == 0) out[b] = -logf(sh[0] * (1.0f / N_));
}

// ---------------- launcher -------------------------------------------------
extern "C" void kernel_launch(void* const* d_in, const int* in_sizes, int n_in,
                              void* d_out, int out_size) {
    const float* fx = (const float*)d_in[0];
    const float* fy = (const float*)d_in[1];
    float* out = (float*)d_out;

    static int configured = 0;
    if (!configured) {
        cudaFuncSetAttribute(k_gemm_mma,
                             cudaFuncAttributeMaxDynamicSharedMemorySize, SM_GEMM);
        configured = 1;
    }

    k_mean_part<<<dim3(NG, B_), 128>>>(fy);
    k_mean_final<<<B_, 128>>>();
    k_normalize<<<(B_ * N_) / 8, 256>>>(fx, fy);
    k_gemm_mma<<<dim3(N_ / 128, N_ / 128, B_), 256, SM_GEMM>>>();
    k_rowpost<<<B_ * N_, 128>>>();
    k_final<<<B_, 128>>>(out);
}

// round 8
// speedup vs baseline: 2.9949x; 1.1694x over previous
#include <cuda_runtime.h>
#include <cuda_fp16.h>
#include <math.h>
#include <stdint.h>

#define B_  4
#define C_  128
#define N_  4096
#define NG  8

// ---------------- scratch (device globals; no allocs) ----------------------
__device__ float   g_part[B_ * NG * C_];
__device__ float   g_mean[B_ * C_];
__device__ __half  g_X[(size_t)B_ * N_ * C_];     // normalized fx, fp16 [b][n][c]
__device__ __half  g_Y[(size_t)B_ * N_ * C_];     // normalized fy, fp16 [b][n][c]
__device__ __half  g_S[(size_t)B_ * N_ * N_];     // similarity, fp16 (128 MB)
__device__ float   g_A[B_ * N_];                  // per-row max(A)

// ---------------- warp MMA helpers (sm_80 PTX: works on compute_103) -------
__device__ __forceinline__ uint32_t smem_to_u32(const void* p) {
    uint32_t a;
    asm("{ .reg .u64 t; cvta.to.shared.u64 t, %1; cvt.u32.u64 %0, t; }"
        : "=r"(a) : "l"(p));
    return a;
}
__device__ __forceinline__ void ldsm4(uint32_t r[4], uint32_t addr) {
    asm volatile("ldmatrix.sync.aligned.m8n8.x4.shared.b16 {%0,%1,%2,%3}, [%4];"
                 : "=r"(r[0]), "=r"(r[1]), "=r"(r[2]), "=r"(r[3]) : "r"(addr));
}
__device__ __forceinline__ void mma16816(float c[4], const uint32_t a[4],
                                         const uint32_t b[2]) {
    asm volatile("mma.sync.aligned.m16n8k16.row.col.f32.f16.f16.f32 "
                 "{%0,%1,%2,%3}, {%4,%5,%6,%7}, {%8,%9}, {%0,%1,%2,%3};"
                 : "+f"(c[0]), "+f"(c[1]), "+f"(c[2]), "+f"(c[3])
                 : "r"(a[0]), "r"(a[1]), "r"(a[2]), "r"(a[3]),
                   "r"(b[0]), "r"(b[1]));
}

// ---------------- kernel 1a/1b: spatial mean of feature_y ------------------
__global__ void k_mean_part(const float* __restrict__ fy) {
    int b = blockIdx.y, g = blockIdx.x, c = threadIdx.x;
    const float* p = fy + ((size_t)b * N_ + (size_t)g * (N_ / NG)) * C_ + c;
    float s = 0.f;
    for (int n = 0; n < N_ / NG; ++n) s += p[(size_t)n * C_];
    g_part[(b * NG + g) * C_ + c] = s;
}
__global__ void k_mean_final() {
    int b = blockIdx.x, c = threadIdx.x;
    float s = 0.f;
    #pragma unroll
    for (int g = 0; g < NG; ++g) s += g_part[(b * NG + g) * C_ + c];
    g_mean[b * C_ + c] = s * (1.0f / N_);
}

// ---------------- kernel 2: center + L2-normalize -> fp16 ------------------
__global__ __launch_bounds__(256) void k_normalize(const float* __restrict__ fx,
                                                   const float* __restrict__ fy) {
    int w    = blockIdx.x * 8 + (threadIdx.x >> 5);
    int lane = threadIdx.x & 31;
    int b = w / N_, n = w % N_;
    size_t base = ((size_t)b * N_ + n) * C_ + lane * 4;
    float4 xv = *(const float4*)(fx + base);
    float4 yv = *(const float4*)(fy + base);
    float4 mv = *(const float4*)(g_mean + b * C_ + lane * 4);
    float cx[4] = {xv.x - mv.x, xv.y - mv.y, xv.z - mv.z, xv.w - mv.w};
    float cy[4] = {yv.x - mv.x, yv.y - mv.y, yv.z - mv.z, yv.w - mv.w};
    float ssx = cx[0]*cx[0] + cx[1]*cx[1] + cx[2]*cx[2] + cx[3]*cx[3];
    float ssy = cy[0]*cy[0] + cy[1]*cy[1] + cy[2]*cy[2] + cy[3]*cy[3];
    #pragma unroll
    for (int o = 16; o; o >>= 1) {
        ssx += __shfl_xor_sync(0xffffffffu, ssx, o);
        ssy += __shfl_xor_sync(0xffffffffu, ssy, o);
    }
    float sx = 1.0f / (sqrtf(ssx) + 1e-10f);
    float sy = 1.0f / (sqrtf(ssy) + 1e-10f);
    __half2 hx0 = __floats2half2_rn(cx[0]*sx, cx[1]*sx);
    __half2 hx1 = __floats2half2_rn(cx[2]*sx, cx[3]*sx);
    __half2 hy0 = __floats2half2_rn(cy[0]*sy, cy[1]*sy);
    __half2 hy1 = __floats2half2_rn(cy[2]*sy, cy[3]*sy);
    *(uint2*)(g_X + base) = make_uint2(*(uint32_t*)&hx0, *(uint32_t*)&hx1);
    *(uint2*)(g_Y + base) = make_uint2(*(uint32_t*)&hy0, *(uint32_t*)&hy1);
}

// ---------------- kernel 3: HMMA GEMM  S = X * Y^T  (fp16 out) -------------
// CTA: 128(n) x 128(m), full K=128 in SMEM. 4 warps = 2(n) x 2(m),
// warp tile 64(n) x 64(m) = 4 x 8 m16n8k16 tiles, 8 k-chunks.
#define SP     272u                 // padded smem row stride in bytes (136 halves)
#define TILE_B (128u * SP)          // 34816 bytes per tile
#define SM_GEMM (2u * TILE_B)       // 69632 bytes

__global__ __launch_bounds__(128, 2) void k_gemm_mma() {
    extern __shared__ char smem[];
    const int tid  = threadIdx.x;
    const int lane = tid & 31, wid = tid >> 5;
    const int b  = blockIdx.z;
    const int n0 = blockIdx.y * 128;
    const int m0 = blockIdx.x * 128;

    // ---- load X/Y tiles (row-major fp16, padded rows) ----
    {
        int row = tid;                  // 0..127, one 256B row each
        const uint4* gx = (const uint4*)(g_X + ((size_t)b * N_ + n0 + row) * C_);
        const uint4* gy = (const uint4*)(g_Y + ((size_t)b * N_ + m0 + row) * C_);
        uint4* sx = (uint4*)(smem + row * SP);
        uint4* sy = (uint4*)(smem + TILE_B + row * SP);
        #pragma unroll
        for (int i = 0; i < 16; ++i) { sx[i] = gx[i]; sy[i] = gy[i]; }
    }
    __syncthreads();

    const int wn0 = (wid & 1) * 64;     // warp n offset
    const int wm0 = (wid >> 1) * 64;    // warp m offset
    uint32_t as_u = smem_to_u32(smem);
    uint32_t bs_u = as_u + TILE_B;

    uint32_t aaddr = as_u + (uint32_t)(wn0 + (lane & 15)) * SP + (uint32_t)(lane >> 4) * 16u;
    uint32_t baddr = bs_u + (uint32_t)(wm0 + ((lane >> 4) & 1) * 8 + (lane & 7)) * SP
                          + (uint32_t)((lane >> 3) & 1) * 16u;

    float acc[4][8][4];
    #pragma unroll
    for (int i = 0; i < 4; ++i)
        #pragma unroll
        for (int j = 0; j < 8; ++j)
            #pragma unroll
            for (int k = 0; k < 4; ++k) acc[i][j][k] = 0.f;

    #pragma unroll
    for (int kc = 0; kc < 8; ++kc) {
        uint32_t koff = (uint32_t)kc * 32u;     // 16 halves per k-chunk
        uint32_t afr[4][4];
        #pragma unroll
        for (int i = 0; i < 4; ++i)
            ldsm4(afr[i], aaddr + (uint32_t)i * (16u * SP) + koff);
        uint32_t bfr[8][2];
        #pragma unroll
        for (int p = 0; p < 4; ++p) {
            uint32_t r[4];
            ldsm4(r, baddr + (uint32_t)p * (16u * SP) + koff);
            bfr[2*p][0]   = r[0]; bfr[2*p][1]   = r[1];
            bfr[2*p+1][0] = r[2]; bfr[2*p+1][1] = r[3];
        }
        #pragma unroll
        for (int i = 0; i < 4; ++i)
            #pragma unroll
            for (int j = 0; j < 8; ++j)
                mma16816(acc[i][j], afr[i], bfr[j]);
    }

    // ---- epilogue: stage fp16 tile in SMEM (conflict-free), store coalesced
    __syncthreads();                    // all warps done reading operands
    #pragma unroll
    for (int i = 0; i < 4; ++i) {
        int r0 = wn0 + i * 16 + (lane >> 2);
        #pragma unroll
        for (int j = 0; j < 8; ++j) {
            int c = wm0 + j * 8 + (lane & 3) * 2;     // half index
            __half2 lo = __floats2half2_rn(acc[i][j][0], acc[i][j][1]);
            __half2 hi = __floats2half2_rn(acc[i][j][2], acc[i][j][3]);
            *(__half2*)(smem + (size_t)r0 * SP + c * 2)       = lo;
            *(__half2*)(smem + (size_t)(r0 + 8) * SP + c * 2) = hi;
        }
    }
    __syncthreads();
    {
        // 16 threads per 256B row, 8 rows per pass, 16 passes
        int rsub = tid >> 4, csub = tid & 15;
        #pragma unroll
        for (int pass = 0; pass < 16; ++pass) {
            int row = pass * 8 + rsub;
            uint4 v = *(const uint4*)(smem + (size_t)row * SP + csub * 16);
            *(uint4*)((char*)(g_S + ((size_t)b * N_ + n0 + row) * N_ + m0) + csub * 16) = v;
        }
    }
}

// ---------------- kernel 4: per-row epilogue (fp16 S) ----------------------
// A_max = 1 / sum_m exp((s_m - smax) * t),  t = 10/(1.001 - smax)
__global__ __launch_bounds__(128) void k_rowpost() {
    const int row = blockIdx.x;
    const int tid = threadIdx.x;
    const uint4* Sr = (const uint4*)(g_S + (size_t)row * N_);

    float f[32];
    float mx = -1e30f;
    #pragma unroll
    for (int k = 0; k < 4; ++k) {
        uint4 v = Sr[tid + k * 128];
        uint32_t u[4] = {v.x, v.y, v.z, v.w};
        #pragma unroll
        for (int j = 0; j < 4; ++j) {
            float2 fv = __half22float2(*(__half2*)&u[j]);
            f[k * 8 + j * 2]     = fv.x;
            f[k * 8 + j * 2 + 1] = fv.y;
            mx = fmaxf(mx, fmaxf(fv.x, fv.y));
        }
    }
    __shared__ float red[128];
    red[tid] = mx; __syncthreads();
    #pragma unroll
    for (int s = 64; s; s >>= 1) {
        if (tid < s) red[tid] = fmaxf(red[tid], red[tid + s]);
        __syncthreads();
    }
    float smax = red[0];
    __syncthreads();
    float t = 10.0f / (1.001f - smax);
    float sum = 0.f;
    #pragma unroll
    for (int i = 0; i < 32; ++i) sum += __expf((f[i] - smax) * t);
    red[tid] = sum; __syncthreads();
    #pragma unroll
    for (int s = 64; s; s >>= 1) {
        if (tid < s) red[tid] += red[tid + s];
        __syncthreads();
    }
    if (tid == 0) g_A[row] = 1.0f / red[0];
}

// ---------------- kernel 5: final CX mean + -log ---------------------------
__global__ void k_final(float* __restrict__ out) {
    int b = blockIdx.x, tid = threadIdx.x;
    float s = 0.f;
    #pragma unroll
    for (int k = 0; k < N_ / 128; ++k) s += g_A[b * N_ + k * 128 + tid];
    __shared__ float sh[128];
    sh[tid] = s; __syncthreads();
    #pragma unroll
    for (int r = 64; r; r >>= 1) {
        if (tid < r) sh[tid] += sh[tid + r];
        __syncthreads();
    }
    if (tid == 0) out[b] = -logf(sh[0] * (1.0f / N_));
}

// ---------------- launcher -------------------------------------------------
extern "C" void kernel_launch(void* const* d_in, const int* in_sizes, int n_in,
                              void* d_out, int out_size) {
    const float* fx = (const float*)d_in[0];
    const float* fy = (const float*)d_in[1];
    float* out = (float*)d_out;

    static int configured = 0;
    if (!configured) {
        cudaFuncSetAttribute(k_gemm_mma,
                             cudaFuncAttributeMaxDynamicSharedMemorySize, SM_GEMM);
        configured = 1;
    }

    k_mean_part<<<dim3(NG, B_), 128>>>(fy);
    k_mean_final<<<B_, 128>>>();
    k_normalize<<<(B_ * N_) / 8, 256>>>(fx, fy);
    k_gemm_mma<<<dim3(N_ / 128, N_ / 128, B_), 128, SM_GEMM>>>();
    k_rowpost<<<B_ * N_, 128>>>();
    k_final<<<B_, 128>>>(out);
}

// round 9
// speedup vs baseline: 3.7933x; 1.2666x over previous
#include <cuda_runtime.h>
#include <cuda_fp16.h>
#include <math.h>
#include <stdint.h>

#define B_  4
#define C_  128
#define N_  4096
#define NG  8

// ---------------- scratch (device globals; no allocs) ----------------------
__device__ float   g_part[B_ * NG * C_];
__device__ float   g_mean[B_ * C_];
__device__ __half  g_X[(size_t)B_ * N_ * C_];     // normalized fx, fp16 [b][n][c]
__device__ __half  g_Y[(size_t)B_ * N_ * C_];     // normalized fy, fp16 [b][n][c]
__device__ float   g_A[B_ * N_];                  // per-row max(A)

// ---------------- warp MMA helpers (sm_80 PTX: works on compute_103) -------
__device__ __forceinline__ uint32_t smem_to_u32(const void* p) {
    uint32_t a;
    asm("{ .reg .u64 t; cvta.to.shared.u64 t, %1; cvt.u32.u64 %0, t; }"
        : "=r"(a) : "l"(p));
    return a;
}
__device__ __forceinline__ void ldsm4(uint32_t r[4], uint32_t addr) {
    asm volatile("ldmatrix.sync.aligned.m8n8.x4.shared.b16 {%0,%1,%2,%3}, [%4];"
                 : "=r"(r[0]), "=r"(r[1]), "=r"(r[2]), "=r"(r[3]) : "r"(addr));
}
__device__ __forceinline__ void mma16816(float c[4], const uint32_t a[4],
                                         const uint32_t b[2]) {
    asm volatile("mma.sync.aligned.m16n8k16.row.col.f32.f16.f16.f32 "
                 "{%0,%1,%2,%3}, {%4,%5,%6,%7}, {%8,%9}, {%0,%1,%2,%3};"
                 : "+f"(c[0]), "+f"(c[1]), "+f"(c[2]), "+f"(c[3])
                 : "r"(a[0]), "r"(a[1]), "r"(a[2]), "r"(a[3]),
                   "r"(b[0]), "r"(b[1]));
}

// ---------------- kernel 1a/1b: spatial mean of feature_y ------------------
__global__ void k_mean_part(const float* __restrict__ fy) {
    int b = blockIdx.y, g = blockIdx.x, c = threadIdx.x;
    const float* p = fy + ((size_t)b * N_ + (size_t)g * (N_ / NG)) * C_ + c;
    float s = 0.f;
    for (int n = 0; n < N_ / NG; ++n) s += p[(size_t)n * C_];
    g_part[(b * NG + g) * C_ + c] = s;
}
__global__ void k_mean_final() {
    int b = blockIdx.x, c = threadIdx.x;
    float s = 0.f;
    #pragma unroll
    for (int g = 0; g < NG; ++g) s += g_part[(b * NG + g) * C_ + c];
    g_mean[b * C_ + c] = s * (1.0f / N_);
}

// ---------------- kernel 2: center + L2-normalize -> fp16 ------------------
__global__ __launch_bounds__(256) void k_normalize(const float* __restrict__ fx,
                                                   const float* __restrict__ fy) {
    int w    = blockIdx.x * 8 + (threadIdx.x >> 5);
    int lane = threadIdx.x & 31;
    int b = w / N_, n = w % N_;
    size_t base = ((size_t)b * N_ + n) * C_ + lane * 4;
    float4 xv = *(const float4*)(fx + base);
    float4 yv = *(const float4*)(fy + base);
    float4 mv = *(const float4*)(g_mean + b * C_ + lane * 4);
    float cx[4] = {xv.x - mv.x, xv.y - mv.y, xv.z - mv.z, xv.w - mv.w};
    float cy[4] = {yv.x - mv.x, yv.y - mv.y, yv.z - mv.z, yv.w - mv.w};
    float ssx = cx[0]*cx[0] + cx[1]*cx[1] + cx[2]*cx[2] + cx[3]*cx[3];
    float ssy = cy[0]*cy[0] + cy[1]*cy[1] + cy[2]*cy[2] + cy[3]*cy[3];
    #pragma unroll
    for (int o = 16; o; o >>= 1) {
        ssx += __shfl_xor_sync(0xffffffffu, ssx, o);
        ssy += __shfl_xor_sync(0xffffffffu, ssy, o);
    }
    float sx = 1.0f / (sqrtf(ssx) + 1e-10f);
    float sy = 1.0f / (sqrtf(ssy) + 1e-10f);
    __half2 hx0 = __floats2half2_rn(cx[0]*sx, cx[1]*sx);
    __half2 hx1 = __floats2half2_rn(cx[2]*sx, cx[3]*sx);
    __half2 hy0 = __floats2half2_rn(cy[0]*sy, cy[1]*sy);
    __half2 hy1 = __floats2half2_rn(cy[2]*sy, cy[3]*sy);
    *(uint2*)(g_X + base) = make_uint2(*(uint32_t*)&hx0, *(uint32_t*)&hx1);
    *(uint2*)(g_Y + base) = make_uint2(*(uint32_t*)&hy0, *(uint32_t*)&hy1);
}

// ---------------- kernel 3: fused strip GEMM + row softmax -----------------
// CTA = 128 n-rows x all 4096 m. 8 warps (2n x 4m), warp tile 64x64,
// step tile 128x256, 16 m-steps, two passes (max, then exp-sum), cp.async
// double-buffered B. No S matrix ever written.
#define SP      272u                  // padded smem row stride (136 halves)
#define A_BYTES (128u * SP)           // 34816
#define SM_B    A_BYTES
#define BUF_B   (256u * SP)           // 69632
#define SM_RED  (SM_B + 2u * BUF_B)   // 174080
#define SM_FUS  (SM_RED + 5120u)      // + maxbuf/sumbuf 2KB each + t/c 1KB

__device__ __forceinline__ void issue_B(int b, int ms, int tid, uint32_t sb) {
    const char* src = (const char*)(g_Y + ((size_t)b * N_ + ms * 256) * C_);
    uint32_t dst = sb + SM_B + (uint32_t)(ms & 1) * BUF_B;
    #pragma unroll
    for (int k = 0; k < 16; ++k) {
        int cidx = tid + k * 256;
        int row = cidx >> 4, c16 = cidx & 15;
        uint32_t d = dst + (uint32_t)row * SP + (uint32_t)c16 * 16u;
        const char* s = src + (size_t)row * 256 + c16 * 16;
        asm volatile("cp.async.cg.shared.global [%0], [%1], 16;"
                     :: "r"(d), "l"(s) : "memory");
    }
    asm volatile("cp.async.commit_group;" ::: "memory");
}

// compute one 128x256 step tile into acc (zeroed here); identical both passes
__device__ __forceinline__ void compute_step(float acc[4][8][4],
                                             uint32_t aaddr, uint32_t baddr) {
    #pragma unroll
    for (int i = 0; i < 4; ++i)
        #pragma unroll
        for (int j = 0; j < 8; ++j)
            #pragma unroll
            for (int k = 0; k < 4; ++k) acc[i][j][k] = 0.f;
    #pragma unroll
    for (int kc = 0; kc < 8; ++kc) {
        uint32_t koff = (uint32_t)kc * 32u;
        uint32_t afr[4][4];
        #pragma unroll
        for (int i = 0; i < 4; ++i)
            ldsm4(afr[i], aaddr + (uint32_t)i * (16u * SP) + koff);
        uint32_t bfr[8][2];
        #pragma unroll
        for (int p = 0; p < 4; ++p) {
            uint32_t r[4];
            ldsm4(r, baddr + (uint32_t)p * (16u * SP) + koff);
            bfr[2*p][0]   = r[0]; bfr[2*p][1]   = r[1];
            bfr[2*p+1][0] = r[2]; bfr[2*p+1][1] = r[3];
        }
        #pragma unroll
        for (int i = 0; i < 4; ++i)
            #pragma unroll
            for (int j = 0; j < 8; ++j)
                mma16816(acc[i][j], afr[i], bfr[j]);
    }
}

__global__ __launch_bounds__(256, 1) void k_fused() {
    extern __shared__ char smem[];
    const int tid  = threadIdx.x;
    const int lane = tid & 31, wid = tid >> 5;
    const int b  = blockIdx.y;
    const int n0 = blockIdx.x * 128;
    uint32_t sb = smem_to_u32(smem);
    const int wn0 = (wid & 1) * 64;
    const int wm0 = (wid >> 1) * 64;
    const int mg  = wid >> 1;            // m-group 0..3

    float* maxbuf = (float*)(smem + SM_RED);
    float* sumbuf = (float*)(smem + SM_RED + 2048);
    float* tvals  = (float*)(smem + SM_RED + 4096);
    float* cvals  = (float*)(smem + SM_RED + 4608);

    // ---- A tile (resident whole kernel) ----
    {
        int row = tid >> 1, off = (tid & 1) * 128;
        const uint4* gx = (const uint4*)((const char*)(g_X + ((size_t)b * N_ + n0 + row) * C_) + off);
        uint4* sx = (uint4*)(smem + row * SP + off);
        #pragma unroll
        for (int i = 0; i < 8; ++i) sx[i] = gx[i];
    }

    uint32_t aaddr = sb + (uint32_t)(wn0 + (lane & 15)) * SP + (uint32_t)(lane >> 4) * 16u;
    uint32_t boff  = (uint32_t)(wm0 + ((lane >> 4) & 1) * 8 + (lane & 7)) * SP
                   + (uint32_t)((lane >> 3) & 1) * 16u;

    // ================= pass 1: per-row max =================
    float rmax[4][2];
    #pragma unroll
    for (int i = 0; i < 4; ++i) { rmax[i][0] = -1e30f; rmax[i][1] = -1e30f; }

    issue_B(b, 0, tid, sb);
    for (int ms = 0; ms < 16; ++ms) {
        asm volatile("cp.async.wait_group 0;" ::: "memory");
        __syncthreads();
        if (ms < 15) issue_B(b, ms + 1, tid, sb);
        float acc[4][8][4];
        compute_step(acc, aaddr, sb + SM_B + (uint32_t)(ms & 1) * BUF_B + boff);
        #pragma unroll
        for (int i = 0; i < 4; ++i)
            #pragma unroll
            for (int j = 0; j < 8; ++j) {
                rmax[i][0] = fmaxf(rmax[i][0], fmaxf(acc[i][j][0], acc[i][j][1]));
                rmax[i][1] = fmaxf(rmax[i][1], fmaxf(acc[i][j][2], acc[i][j][3]));
            }
    }
    #pragma unroll
    for (int i = 0; i < 4; ++i)
        #pragma unroll
        for (int z = 0; z < 2; ++z) {
            rmax[i][z] = fmaxf(rmax[i][z], __shfl_xor_sync(0xffffffffu, rmax[i][z], 1));
            rmax[i][z] = fmaxf(rmax[i][z], __shfl_xor_sync(0xffffffffu, rmax[i][z], 2));
        }
    if ((lane & 3) == 0) {
        #pragma unroll
        for (int i = 0; i < 4; ++i) {
            int r = wn0 + i * 16 + (lane >> 2);
            maxbuf[mg * 128 + r]     = rmax[i][0];
            maxbuf[mg * 128 + r + 8] = rmax[i][1];
        }
    }
    __syncthreads();
    if (tid < 128) {
        float m = fmaxf(fmaxf(maxbuf[tid], maxbuf[128 + tid]),
                        fmaxf(maxbuf[256 + tid], maxbuf[384 + tid]));
        float t = 10.0f / (1.001f - m);
        tvals[tid] = t;
        cvals[tid] = -m * t;
    }
    __syncthreads();

    float tA[4], cA[4], tB[4], cB[4];
    #pragma unroll
    for (int i = 0; i < 4; ++i) {
        int r = wn0 + i * 16 + (lane >> 2);
        tA[i] = tvals[r];     cA[i] = cvals[r];
        tB[i] = tvals[r + 8]; cB[i] = cvals[r + 8];
    }

    // ================= pass 2: exp-sum (bit-identical recompute) ===========
    float rsum[4][2];
    #pragma unroll
    for (int i = 0; i < 4; ++i) { rsum[i][0] = 0.f; rsum[i][1] = 0.f; }

    issue_B(b, 0, tid, sb);
    for (int ms = 0; ms < 16; ++ms) {
        asm volatile("cp.async.wait_group 0;" ::: "memory");
        __syncthreads();
        if (ms < 15) issue_B(b, ms + 1, tid, sb);
        float acc[4][8][4];
        compute_step(acc, aaddr, sb + SM_B + (uint32_t)(ms & 1) * BUF_B + boff);
        #pragma unroll
        for (int i = 0; i < 4; ++i)
            #pragma unroll
            for (int j = 0; j < 8; ++j) {
                rsum[i][0] += __expf(fmaf(acc[i][j][0], tA[i], cA[i]))
                            + __expf(fmaf(acc[i][j][1], tA[i], cA[i]));
                rsum[i][1] += __expf(fmaf(acc[i][j][2], tB[i], cB[i]))
                            + __expf(fmaf(acc[i][j][3], tB[i], cB[i]));
            }
    }
    #pragma unroll
    for (int i = 0; i < 4; ++i)
        #pragma unroll
        for (int z = 0; z < 2; ++z) {
            rsum[i][z] += __shfl_xor_sync(0xffffffffu, rsum[i][z], 1);
            rsum[i][z] += __shfl_xor_sync(0xffffffffu, rsum[i][z], 2);
        }
    if ((lane & 3) == 0) {
        #pragma unroll
        for (int i = 0; i < 4; ++i) {
            int r = wn0 + i * 16 + (lane >> 2);
            sumbuf[mg * 128 + r]     = rsum[i][0];
            sumbuf[mg * 128 + r + 8] = rsum[i][1];
        }
    }
    __syncthreads();
    if (tid < 128) {
        float s = (sumbuf[tid] + sumbuf[128 + tid])
                + (sumbuf[256 + tid] + sumbuf[384 + tid]);
        g_A[b * N_ + n0 + tid] = 1.0f / s;
    }
}

// ---------------- kernel 5: final CX mean + -log ---------------------------
__global__ void k_final(float* __restrict__ out) {
    int b = blockIdx.x, tid = threadIdx.x;
    float s = 0.f;
    #pragma unroll
    for (int k = 0; k < N_ / 128; ++k) s += g_A[b * N_ + k * 128 + tid];
    __shared__ float sh[128];
    sh[tid] = s; __syncthreads();
    #pragma unroll
    for (int r = 64; r; r >>= 1) {
        if (tid < r) sh[tid] += sh[tid + r];
        __syncthreads();
    }
    if (tid == 0) out[b] = -logf(sh[0] * (1.0f / N_));
}

// ---------------- launcher -------------------------------------------------
extern "C" void kernel_launch(void* const* d_in, const int* in_sizes, int n_in,
                              void* d_out, int out_size) {
    const float* fx = (const float*)d_in[0];
    const float* fy = (const float*)d_in[1];
    float* out = (float*)d_out;

    static int configured = 0;
    if (!configured) {
        cudaFuncSetAttribute(k_fused,
                             cudaFuncAttributeMaxDynamicSharedMemorySize, SM_FUS);
        configured = 1;
    }

    k_mean_part<<<dim3(NG, B_), 128>>>(fy);
    k_mean_final<<<B_, 128>>>();
    k_normalize<<<(B_ * N_) / 8, 256>>>(fx, fy);
    k_fused<<<dim3(N_ / 128, B_), 256, SM_FUS>>>();
    k_final<<<B_, 128>>>(out);
}